// round 14
// baseline (speedup 1.0000x reference)
#include <cuda_runtime.h>
#include <math.h>
#include <stdint.h>

#define NTOK 32768
#define DIM  1024
#define HID  256
#define NEXP 64

#define TM   64
#define KC   32
#define NTHR 256

#define AS_STRIDE 36    // float2 units per token row (A staged, duplicated pairs)
#define WS_STRIDE 260   // floats per k-row of transposed W1 tile
#define HS_STRIDE 268   // floats per token row of h
#define LS_STRIDE 65    // floats per token row of logits

// float offsets within dynamic smem
#define WS_OFF  4608                  // ASP occupies [0, 4608) floats (2304 float2)
#define HS_OFF  0                     // reused after phase 1: 64*268 = 17152
#define W2_OFF  17152                 // 64*256 = 16384
#define LS_OFF  33536                 // 64*65  = 4160
#define SMEM_FLOATS 37696
#define SMEM_BYTES (SMEM_FLOATS * 4)

#define FMA2(d, a, b) asm("fma.rn.f32x2 %0, %1, %2, %0;" : "+l"(d) : "l"(a), "l"(b))

__global__ __launch_bounds__(NTHR, 1)
void gating_fused_kernel(const float* __restrict__ x,
                         const float* __restrict__ w1,
                         const float* __restrict__ b1,
                         const float* __restrict__ w2,
                         const float* __restrict__ b2,
                         float* __restrict__ out)
{
    extern __shared__ float sm[];
    float2* asp = reinterpret_cast<float2*>(sm);   // [64][AS_STRIDE] float2 {a,a}
    float*  ws  = sm + WS_OFF;                     // [KC][WS_STRIDE]
    float*  hs  = sm + HS_OFF;                     // [64][HS_STRIDE]
    float*  w2s = sm + W2_OFF;                     // [64][256]
    float*  ls  = sm + LS_OFF;                     // [64][LS_STRIDE]

    const int tid  = threadIdx.x;
    const int tok0 = blockIdx.x * TM;

    // ---- stage w2 into smem (region disjoint from phase-1 staging buffers) ----
    {
        const float4* src = reinterpret_cast<const float4*>(w2);
        float4* dst = reinterpret_cast<float4*>(w2s);
        #pragma unroll
        for (int i = 0; i < 16; ++i)
            dst[tid + NTHR * i] = src[tid + NTHR * i];
    }

    const int col_t = tid & 31;   // hidden-col group (0..31)
    const int row_t = tid >> 5;   // token-row group (0..7)

    // staging maps
    const int xr_row = tid >> 3;  // 0..31
    const int xr_c4  = tid & 7;   // k-granule 0..7
    const int w_c4   = tid & 7;
    const int w_h0   = tid >> 3;  // 0..31

    const float* xbase = x + (size_t)tok0 * DIM;

    float4 xr[2], wr[8];

    // preload chunk 0
    {
        xr[0] = *reinterpret_cast<const float4*>(xbase + (size_t)xr_row * DIM + xr_c4 * 4);
        xr[1] = *reinterpret_cast<const float4*>(xbase + (size_t)(xr_row + 32) * DIM + xr_c4 * 4);
        #pragma unroll
        for (int i = 0; i < 8; ++i)
            wr[i] = *reinterpret_cast<const float4*>(w1 + (size_t)(w_h0 + 32 * i) * DIM + w_c4 * 4);
    }

    unsigned long long acc[8][4];
    #pragma unroll
    for (int i = 0; i < 8; ++i)
        #pragma unroll
        for (int j = 0; j < 4; ++j)
            acc[i][j] = 0ull;

    #pragma unroll 1
    for (int ch = 0; ch < DIM / KC; ++ch) {
        __syncthreads();
        // store staged tile to smem
        {
            float4 v = xr[0];
            int base = xr_row * AS_STRIDE + xr_c4 * 4;
            asp[base + 0] = make_float2(v.x, v.x);
            asp[base + 1] = make_float2(v.y, v.y);
            asp[base + 2] = make_float2(v.z, v.z);
            asp[base + 3] = make_float2(v.w, v.w);
            v = xr[1];
            base = (xr_row + 32) * AS_STRIDE + xr_c4 * 4;
            asp[base + 0] = make_float2(v.x, v.x);
            asp[base + 1] = make_float2(v.y, v.y);
            asp[base + 2] = make_float2(v.z, v.z);
            asp[base + 3] = make_float2(v.w, v.w);
        }
        #pragma unroll
        for (int i = 0; i < 8; ++i) {
            float4 v = wr[i];
            int h = w_h0 + 32 * i;
            ws[(w_c4 * 4 + 0) * WS_STRIDE + h] = v.x;
            ws[(w_c4 * 4 + 1) * WS_STRIDE + h] = v.y;
            ws[(w_c4 * 4 + 2) * WS_STRIDE + h] = v.z;
            ws[(w_c4 * 4 + 3) * WS_STRIDE + h] = v.w;
        }
        __syncthreads();

        // prefetch next chunk (LDG latency hidden behind compute)
        if (ch + 1 < DIM / KC) {
            int kc0 = (ch + 1) * KC;
            xr[0] = *reinterpret_cast<const float4*>(xbase + (size_t)xr_row * DIM + kc0 + xr_c4 * 4);
            xr[1] = *reinterpret_cast<const float4*>(xbase + (size_t)(xr_row + 32) * DIM + kc0 + xr_c4 * 4);
            #pragma unroll
            for (int i = 0; i < 8; ++i)
                wr[i] = *reinterpret_cast<const float4*>(w1 + (size_t)(w_h0 + 32 * i) * DIM + kc0 + w_c4 * 4);
        }

        // compute: 32 k-steps, 64 FMA each via FFMA2
        #pragma unroll
        for (int k = 0; k < KC; ++k) {
            unsigned long long a[8];
            #pragma unroll
            for (int i = 0; i < 4; ++i) {
                a[i]     = *reinterpret_cast<const unsigned long long*>(&asp[(row_t * 4 + i) * AS_STRIDE + k]);
                a[4 + i] = *reinterpret_cast<const unsigned long long*>(&asp[(row_t * 4 + 32 + i) * AS_STRIDE + k]);
            }
            ulonglong2 bv0 = *reinterpret_cast<const ulonglong2*>(&ws[k * WS_STRIDE + col_t * 4]);
            ulonglong2 bv1 = *reinterpret_cast<const ulonglong2*>(&ws[k * WS_STRIDE + 128 + col_t * 4]);
            #pragma unroll
            for (int i = 0; i < 8; ++i) {
                FMA2(acc[i][0], a[i], bv0.x);
                FMA2(acc[i][1], a[i], bv0.y);
                FMA2(acc[i][2], a[i], bv1.x);
                FMA2(acc[i][3], a[i], bv1.y);
            }
        }
    }
    __syncthreads();  // all compute reads of asp/ws done before hs overwrites them

    // ---- epilogue: bias + relu, write h to smem ----
    {
        float4 bg0 = *reinterpret_cast<const float4*>(&b1[col_t * 4]);
        float4 bg1 = *reinterpret_cast<const float4*>(&b1[128 + col_t * 4]);
        #pragma unroll
        for (int i = 0; i < 8; ++i) {
            int r = (i < 4) ? (row_t * 4 + i) : (row_t * 4 + 32 + (i - 4));
            float2 p0 = *reinterpret_cast<float2*>(&acc[i][0]);
            float2 p1 = *reinterpret_cast<float2*>(&acc[i][1]);
            float2 p2 = *reinterpret_cast<float2*>(&acc[i][2]);
            float2 p3 = *reinterpret_cast<float2*>(&acc[i][3]);
            float4 h0 = make_float4(fmaxf(p0.x + bg0.x, 0.f), fmaxf(p0.y + bg0.y, 0.f),
                                    fmaxf(p1.x + bg0.z, 0.f), fmaxf(p1.y + bg0.w, 0.f));
            float4 h1 = make_float4(fmaxf(p2.x + bg1.x, 0.f), fmaxf(p2.y + bg1.y, 0.f),
                                    fmaxf(p3.x + bg1.z, 0.f), fmaxf(p3.y + bg1.w, 0.f));
            *reinterpret_cast<float4*>(&hs[r * HS_STRIDE + col_t * 4]) = h0;
            *reinterpret_cast<float4*>(&hs[r * HS_STRIDE + 128 + col_t * 4]) = h1;
        }
    }
    __syncthreads();

    // ---- phase 2: logits = h @ w2^T + b2 (pairs packed along K) ----
    {
        const int m = tid & 63;
        const int g = tid >> 6;             // expert group 0..3 (16 experts each)
        const float* hrow  = hs + m * HS_STRIDE;
        const float* wbase = w2s + g * 16 * HID;

        unsigned long long acc2[16];
        #pragma unroll
        for (int j = 0; j < 16; ++j) acc2[j] = 0ull;

        #pragma unroll 4
        for (int k = 0; k < HID; k += 4) {
            ulonglong2 hv = *reinterpret_cast<const ulonglong2*>(hrow + k);
            #pragma unroll
            for (int j = 0; j < 16; ++j) {
                ulonglong2 w = *reinterpret_cast<const ulonglong2*>(wbase + j * HID + k);
                FMA2(acc2[j], hv.x, w.x);
                FMA2(acc2[j], hv.y, w.y);
            }
        }
        #pragma unroll
        for (int j = 0; j < 16; ++j) {
            float2 p = *reinterpret_cast<float2*>(&acc2[j]);
            int e = g * 16 + j;
            ls[m * LS_STRIDE + e] = p.x + p.y + __ldg(&b2[e]);
        }
    }
    __syncthreads();

    // ---- phase 3: top-2 + softmax over top-2 (JAX tie-break: lowest index) ----
    if (tid < TM) {
        const float* lr = ls + tid * LS_STRIDE;
        float v0 = -1e30f; int i0 = 0;
        #pragma unroll
        for (int e = 0; e < NEXP; ++e) {
            float v = lr[e];
            if (v > v0) { v0 = v; i0 = e; }
        }
        float v1 = -1e30f; int i1 = 0;
        #pragma unroll
        for (int e = 0; e < NEXP; ++e) {
            if (e == i0) continue;
            float v = lr[e];
            if (v > v1) { v1 = v; i1 = e; }
        }
        int gt = tok0 + tid;
        float t   = expf(v1 - v0);
        float inv = 1.0f / (1.0f + t);
        // outputs concatenated: [top_k_indices (N,2) as float | top_k_gates (N,2)]
        out[2 * gt]     = (float)i0;
        out[2 * gt + 1] = (float)i1;
        out[2 * NTOK + 2 * gt]     = inv;       // softmax of max logit
        out[2 * NTOK + 2 * gt + 1] = t * inv;   // softmax of 2nd logit
    }
}

extern "C" void kernel_launch(void* const* d_in, const int* in_sizes, int n_in,
                              void* d_out, int out_size) {
    const float* x  = (const float*)d_in[0];
    const float* w1 = (const float*)d_in[1];
    const float* b1 = (const float*)d_in[2];
    const float* w2 = (const float*)d_in[3];
    const float* b2 = (const float*)d_in[4];
    float* out = (float*)d_out;

    cudaFuncSetAttribute(gating_fused_kernel,
                         cudaFuncAttributeMaxDynamicSharedMemorySize, SMEM_BYTES);
    gating_fused_kernel<<<NTOK / TM, NTHR, SMEM_BYTES>>>(x, w1, b1, w2, b2, out);
}